// round 3
// baseline (speedup 1.0000x reference)
#include <cuda_runtime.h>
#include <math.h>

#define NN    8192
#define NL    16
#define NE    (NN * 128)         /* 1048576 edges per layer */
#define NOUT  16
#define EOUT  (NN * NOUT)        /* 131072 output edges */

// Triple-buffered node accumulators + output logit accumulator (scratch; no allocs allowed)
__device__ float g_buf[3][NN];
__device__ float g_oacc[NOUT];

__device__ __forceinline__ float lrelu(float v) { return v >= 0.f ? v : 0.01f * v; }

// Zero g_buf[1] (target of layer 0) and the output accumulator.
__global__ void init_kernel() {
    int i = blockIdx.x * blockDim.x + threadIdx.x;
    if (i < NN) g_buf[1][i] = 0.f;
    if (i < NOUT) g_oacc[i] = 0.f;
}

// One hidden layer: stage lrelu(vin) into smem, zero the buffer that layer l+1
// will scatter into, then scatter-add 1M edges with global float atomics.
__global__ void __launch_bounds__(1024, 1) layer_kernel(
    const int4*  __restrict__ src,
    const int4*  __restrict__ dst,
    const float4* __restrict__ w,
    const float* __restrict__ vin,
    float*       __restrict__ vout,
    float*       __restrict__ vzero,
    int apply_act)
{
    __shared__ float s_vals[NN];
    const int tid = threadIdx.x;

    // Stage node values (vectorized), applying the activation of the previous layer.
    const float4* vin4 = (const float4*)vin;
    float4* s4 = (float4*)s_vals;
    #pragma unroll
    for (int i = tid; i < NN / 4; i += 1024) {
        float4 v = vin4[i];
        if (apply_act) {
            v.x = lrelu(v.x); v.y = lrelu(v.y); v.z = lrelu(v.z); v.w = lrelu(v.w);
        }
        s4[i] = v;
    }

    // Fused zeroing of the next layer's scatter target (distinct from vin/vout).
    const int g  = blockIdx.x * blockDim.x + tid;
    const int gs = gridDim.x * blockDim.x;
    for (int i = g; i < NN; i += gs) vzero[i] = 0.f;

    __syncthreads();

    const int EV = NE / 4;
    for (int i = g; i < EV; i += gs) {
        int4   s  = src[i];
        int4   d  = dst[i];
        float4 ww = w[i];
        atomicAdd(&vout[d.x], s_vals[s.x] * ww.x);
        atomicAdd(&vout[d.y], s_vals[s.y] * ww.y);
        atomicAdd(&vout[d.z], s_vals[s.z] * ww.z);
        atomicAdd(&vout[d.w], s_vals[s.w] * ww.w);
    }
}

// Output layer: 131072 edges into 16 logits. Per-CTA smem bins, one global
// atomic merge per bin per CTA.
__global__ void __launch_bounds__(256) out_kernel(
    const int*   __restrict__ osrc,
    const int*   __restrict__ odst,
    const float* __restrict__ ow,
    const float* __restrict__ vin)
{
    __shared__ float s_acc[NOUT];
    if (threadIdx.x < NOUT) s_acc[threadIdx.x] = 0.f;
    __syncthreads();

    const int g  = blockIdx.x * blockDim.x + threadIdx.x;
    const int gs = gridDim.x * blockDim.x;
    for (int i = g; i < EOUT; i += gs) {
        float v = lrelu(vin[osrc[i]]);      // vin table is L2/L1-hot (32 KB)
        atomicAdd(&s_acc[odst[i]], v * ow[i]);
    }
    __syncthreads();
    if (threadIdx.x < NOUT) atomicAdd(&g_oacc[threadIdx.x], s_acc[threadIdx.x]);
}

// lrelu + softmax over the 16 logits; one warp.
__global__ void softmax_kernel(float* __restrict__ out) {
    const int t = threadIdx.x;                  // 32 threads
    float v = (t < NOUT) ? lrelu(g_oacc[t]) : -INFINITY;
    float m = v;
    #pragma unroll
    for (int o = 8; o > 0; o >>= 1) m = fmaxf(m, __shfl_xor_sync(0xffffffffu, m, o));
    float e = (t < NOUT) ? __expf(v - m) : 0.f;
    float s = e;
    #pragma unroll
    for (int o = 8; o > 0; o >>= 1) s += __shfl_xor_sync(0xffffffffu, s, o);
    if (t < NOUT) out[t] = e / s;
}

extern "C" void kernel_launch(void* const* d_in, const int* in_sizes, int n_in,
                              void* d_out, int out_size)
{
    // metadata order: x, edge_w, out_w, edge_src, edge_dst, out_src, out_dst
    const float* x        = (const float*)d_in[0];
    const float* edge_w   = (const float*)d_in[1];
    const float* out_w    = (const float*)d_in[2];
    const int*   edge_src = (const int*)  d_in[3];
    const int*   edge_dst = (const int*)  d_in[4];
    const int*   out_src  = (const int*)  d_in[5];
    const int*   out_dst  = (const int*)  d_in[6];
    float* out = (float*)d_out;

    float* buf = nullptr;
    cudaGetSymbolAddress((void**)&buf, g_buf);   // not a stream op; capture-safe

    init_kernel<<<(NN + 255) / 256, 256>>>();

    for (int l = 0; l < NL; ++l) {
        const float* vin  = (l == 0) ? x : (buf + (size_t)(l % 3) * NN);
        float*       vout = buf + (size_t)((l + 1) % 3) * NN;
        float*       vz   = buf + (size_t)((l + 2) % 3) * NN;
        const size_t off  = (size_t)l * NE;
        layer_kernel<<<152, 1024>>>(
            (const int4*)(edge_src + off),
            (const int4*)(edge_dst + off),
            (const float4*)(edge_w + off),
            vin, vout, vz, (l > 0) ? 1 : 0);
    }

    // Final hidden values live (raw, pre-activation) in g_buf[(NL) % 3] == g_buf[1]
    out_kernel<<<152, 256>>>(out_src, out_dst, out_w, buf + (size_t)(NL % 3) * NN);
    softmax_kernel<<<1, 32>>>(out);
}